// round 14
// baseline (speedup 1.0000x reference)
#include <cuda_runtime.h>
#include <cstdint>

#define NUM_INPUT  700
#define NUM_HIDDEN 256
#define NUM_OUTPUT 20
#define WIN        50
#define BATCH      512
#define THRESH     0.3f
#define ALPHA      0.8f

#define M_ROWS (BATCH * WIN)   // 25600

typedef unsigned long long ull;

// ---------------- f32x2 helpers ----------------
__device__ __forceinline__ ull pack2(float x, float y) {
    ull r; asm("mov.b64 %0, {%1, %2};" : "=l"(r) : "f"(x), "f"(y)); return r;
}
__device__ __forceinline__ void unpack2(ull v, float& x, float& y) {
    asm("mov.b64 {%0, %1}, %2;" : "=f"(x), "=f"(y) : "l"(v));
}
__device__ __forceinline__ void ffma2(ull& d, ull a, ull b) {   // d = a*b + d
    asm("fma.rn.f32x2 %0, %1, %2, %0;" : "+l"(d) : "l"(a), "l"(b));
}
__device__ __forceinline__ ull fma2n(ull a, ull b, ull c) {     // a*b + c
    ull d; asm("fma.rn.f32x2 %0, %1, %2, %3;" : "=l"(d) : "l"(a), "l"(b), "l"(c)); return d;
}
__device__ __forceinline__ ull add2(ull a, ull b) {
    ull d; asm("add.rn.f32x2 %0, %1, %2;" : "=l"(d) : "l"(a), "l"(b)); return d;
}
__device__ __forceinline__ ulonglong2 ldg128(const float* p) {
    ulonglong2 v;
    asm("ld.global.nc.v2.u64 {%0, %1}, [%2];" : "=l"(v.x), "=l"(v.y) : "l"(p));
    return v;
}
// coherent (L2) 128-bit load: for data written earlier in the SAME launch
__device__ __forceinline__ float4 ldg_cg128(const float* p) {
    float4 v;
    asm volatile("ld.global.cg.v4.f32 {%0,%1,%2,%3}, [%4];"
                 : "=f"(v.x), "=f"(v.y), "=f"(v.z), "=f"(v.w) : "l"(p));
    return v;
}

// ---------------- device scratch ----------------
__device__ float g_WcT[3 * NUM_INPUT * NUM_HIDDEN];
__device__ float g_WfT[2 * NUM_HIDDEN * NUM_HIDDEN];
__device__ float g_WrT[2 * NUM_HIDDEN * NUM_HIDDEN];
__device__ float g_WoT[NUM_HIDDEN * NUM_OUTPUT];
__device__ float g_cvec[NUM_HIDDEN];
__device__ float g_ff0[M_ROWS * NUM_HIDDEN];
__device__ int   g_flags[4 * WIN];          // per (t, chunk) tile counter (2 colhalves)

// ---------------- prep kernels ----------------
__global__ void prep_transpose(const float* __restrict__ Wf,
                               const float* __restrict__ Wr,
                               const float* __restrict__ Wo) {
    int idx = blockIdx.x * 256 + threadIdx.x;
    if (idx < 4 * WIN) g_flags[idx] = 0;
    if (idx < 2 * 256 * 256) {
        int h = idx & 255;
        int k = (idx >> 8) & 255;
        int l = idx >> 16;
        g_WfT[(l * 256 + k) * 256 + h] = Wf[(l * 256 + h) * 256 + k];
        g_WrT[(l * 256 + k) * 256 + h] = Wr[(l * 256 + h) * 256 + k];
    }
    if (idx < 256 * 20) {
        int o = idx % 20;
        int k = idx / 20;
        g_WoT[k * 20 + o] = Wo[o * 256 + k];
    }
}

// wc blocks 0..2099, cvec block 2100 (bit-identical to the R11 separate kernels)
__global__ void prep_wc_cvec(const float* __restrict__ Wd,
                             const float* __restrict__ bd,
                             const float* __restrict__ bf) {
    if (blockIdx.x < 3 * NUM_INPUT) {
        int ik = blockIdx.x;
        int i = ik / NUM_INPUT;
        int k = ik % NUM_INPUT;
        int h = threadIdx.x;
        float s = 0.f;
#pragma unroll 8
        for (int j = 0; j < 256; j++) {
            s += g_WfT[j * 256 + h] * __ldg(&Wd[(i * 256 + j) * NUM_INPUT + k]);
        }
        g_WcT[(i * NUM_INPUT + k) * 256 + h] = s;
    } else {
        int h = threadIdx.x;
        float s = bf[h];
#pragma unroll 8
        for (int j = 0; j < 256; j++) {
            float bsum = bd[j] + bd[256 + j] + bd[512 + j];
            s += bsum * g_WfT[j * 256 + h];
        }
        g_cvec[h] = s;
    }
}

// ---------------- fused kernel ----------------
// blocks 0..63: scan (one per 8 batch rows). blocks 64..463: gemm tiles.
// gemm tile gid-64: tile = (gid-64)>>1 in t-ascending order, colhalf = (gid-64)&1.
#define FK_SCAN_BLOCKS 64
#define FK_GEMM_BLOCKS 400

// scan smem layout (floats)
#define OFFP    0
#define OFFS0   16384
#define OFFS1   (OFFS0 + 5120)
#define OFFWOT  (OFFS1 + 5120)
#define OFFOSM  (OFFWOT + 5120)
#define OFFOTMP (OFFOSM + 160)
#define SCAN_FLOATS (OFFOTMP + 160)    // 32064 floats = 128256 bytes

__device__ __forceinline__ void accum_quad_pf(ull acc[8][2], const float* __restrict__ wg,
                                              int hq4, const float* __restrict__ sp, int kbeg) {
    const float* wp = wg + (size_t)kbeg * 256 + hq4;
    ulonglong2 wbuf[2][4];
#pragma unroll
    for (int cc = 0; cc < 4; cc++) wbuf[0][cc] = ldg128(wp + cc * 256);
#pragma unroll
    for (int j = 0; j < 8; j++) {
        const int cur = j & 1, nxt = cur ^ 1;
        if (j < 7) {
            const float* q = wp + (size_t)((j + 1) * 4) * 256;
#pragma unroll
            for (int cc = 0; cc < 4; cc++) wbuf[nxt][cc] = ldg128(q + cc * 256);
        }
#pragma unroll
        for (int cc = 0; cc < 4; cc++) {
            const int k = kbeg + j * 4 + cc;
            const ulonglong2* sq = (const ulonglong2*)(sp + k * 20);
            ulonglong2 s01 = sq[0], s23 = sq[1], s45 = sq[2], s67 = sq[3];
            ulonglong2 w = wbuf[cur][cc];
            ffma2(acc[0][0], w.x, s01.x); ffma2(acc[0][1], w.y, s01.x);
            ffma2(acc[1][0], w.x, s01.y); ffma2(acc[1][1], w.y, s01.y);
            ffma2(acc[2][0], w.x, s23.x); ffma2(acc[2][1], w.y, s23.x);
            ffma2(acc[3][0], w.x, s23.y); ffma2(acc[3][1], w.y, s23.y);
            ffma2(acc[4][0], w.x, s45.x); ffma2(acc[4][1], w.y, s45.x);
            ffma2(acc[5][0], w.x, s45.y); ffma2(acc[5][1], w.y, s45.y);
            ffma2(acc[6][0], w.x, s67.x); ffma2(acc[6][1], w.y, s67.x);
            ffma2(acc[7][0], w.x, s67.y); ffma2(acc[7][1], w.y, s67.y);
        }
    }
}

__global__ __launch_bounds__(512, 1) void fused_kernel(const float* __restrict__ x,
                                                       const float* __restrict__ bf,
                                                       const float* __restrict__ bo,
                                                       float* __restrict__ out) {
    extern __shared__ float sm[];
    const int tid = threadIdx.x;

    if (blockIdx.x >= FK_SCAN_BLOCKS) {
        // ==================== GEMM tile (128 rows x 128 cols, dup-B) =========
        const int gid = blockIdx.x - FK_SCAN_BLOCKS;
        const int tile = gid >> 1;              // 0..199, t-ascending
        const int h0 = (gid & 1) << 7;          // 0 or 128
        const int t = tile >> 2;
        const int b0g = (tile & 3) << 7;

        float (*As)[132] = reinterpret_cast<float(*)[132]>(sm);
        float (*Bs)[256] = reinterpret_cast<float(*)[256]>(sm + 16 * 132);  // DUPLICATED

        const int lane = tid & 31;
        const int warp = tid >> 5;
        const int arow = tid >> 2;              // 0..127
        const int akq  = (tid & 3) * 4;         // 0,4,8,12
        const int bk   = tid >> 5;              // 0..15
        const int bcol = lane * 4;

        ull accp[4][4];
#pragma unroll
        for (int p = 0; p < 4; p++)
#pragma unroll
            for (int j = 0; j < 4; j++) accp[p][j] = 0ull;

        for (int seg = 0; seg < 3; seg++) {
            const int d = seg * 16;
            if (t < d) continue;
            const int ts = t - d;
            const float* __restrict__ xrow = x + ((size_t)(b0g + arow) * WIN + ts) * NUM_INPUT;
            const float* __restrict__ Bsrc = g_WcT + (size_t)seg * NUM_INPUT * 256;

            for (int kb = 0; kb < 704; kb += 16) {
                int kg = kb + akq;
                float4 v = make_float4(0.f, 0.f, 0.f, 0.f);
                if (kg < NUM_INPUT) v = __ldg((const float4*)(xrow + kg));
                As[akq + 0][arow] = v.x;
                As[akq + 1][arow] = v.y;
                As[akq + 2][arow] = v.z;
                As[akq + 3][arow] = v.w;

                int kg2 = kb + bk;
                float4 w = make_float4(0.f, 0.f, 0.f, 0.f);
                if (kg2 < NUM_INPUT)
                    w = __ldg((const float4*)(Bsrc + (size_t)kg2 * 256 + h0 + bcol));
                // store DUPLICATED pairs: ready-made FFMA2 operands
                *(float4*)&Bs[bk][bcol * 2]     = make_float4(w.x, w.x, w.y, w.y);
                *(float4*)&Bs[bk][bcol * 2 + 4] = make_float4(w.z, w.z, w.w, w.w);

                __syncthreads();
#pragma unroll
                for (int kk = 0; kk < 16; kk++) {
                    ulonglong2 a01 = *(const ulonglong2*)&As[kk][warp * 8 + 0];
                    ulonglong2 a23 = *(const ulonglong2*)&As[kk][warp * 8 + 4];
                    ulonglong2 b01 = *(const ulonglong2*)&Bs[kk][lane * 8 + 0];
                    ulonglong2 b23 = *(const ulonglong2*)&Bs[kk][lane * 8 + 4];
                    ull bp[4] = {b01.x, b01.y, b23.x, b23.y};
                    ull ap[4] = {a01.x, a01.y, a23.x, a23.y};
#pragma unroll
                    for (int p = 0; p < 4; p++)
#pragma unroll
                        for (int j = 0; j < 4; j++) ffma2(accp[p][j], ap[p], bp[j]);
                }
                __syncthreads();
            }
        }

        // epilogue: + cvec, store t-major rows; then publish flag
        {
            float4 cv = __ldg((const float4*)(g_cvec + h0 + lane * 4));
#pragma unroll
            for (int p = 0; p < 4; p++) {
                float lo[4], hi[4];
#pragma unroll
                for (int j = 0; j < 4; j++) unpack2(accp[p][j], lo[j], hi[j]);
                float4 o0 = make_float4(lo[0] + cv.x, lo[1] + cv.y, lo[2] + cv.z, lo[3] + cv.w);
                float4 o1 = make_float4(hi[0] + cv.x, hi[1] + cv.y, hi[2] + cv.z, hi[3] + cv.w);
                int r0 = b0g + warp * 8 + 2 * p;
                *(float4*)(g_ff0 + ((size_t)r0 * WIN + t) * 256 + h0 + lane * 4) = o0;
                *(float4*)(g_ff0 + ((size_t)(r0 + 1) * WIN + t) * 256 + h0 + lane * 4) = o1;
            }
        }
        __threadfence();
        __syncthreads();
        if (tid == 0) atomicAdd(&g_flags[tile], 1);
        return;
    }

    // ==================== SCAN block (R11 exact) ====================
    ulonglong2* partq = (ulonglong2*)(sm + OFFP);
    float* sp0  = sm + OFFS0;
    float* sp1  = sm + OFFS1;
    float* wot  = sm + OFFWOT;
    float* opart = sm + OFFP;          // alias (barrier-separated)
    float* osm  = sm + OFFOSM;
    float* otmp = sm + OFFOTMP;

    const int ks = tid >> 6;
    const int hq = tid & 63;
    const int hq4 = hq * 4;
    const int b0 = blockIdx.x * 8;
    const int chunk = blockIdx.x >> 4;         // 128-batch chunk

    for (int i = tid; i < 256 * 20; i += 512) wot[i] = g_WoT[i];
    for (int i = tid; i < 5120; i += 512) { sp0[i] = 0.f; sp1[i] = 0.f; }
    __syncthreads();

    ull m0a = 0, m0b = 0, m1a = 0, m1b = 0;
    const ull alpha2 = pack2(ALPHA, ALPHA);
    ull df0a = alpha2, df0b = alpha2, df1a = alpha2, df1b = alpha2;

    float4 bfq = __ldg((const float4*)(bf + 256 + hq4));
    const ull bf1a = pack2(bfq.x, bfq.y);
    const ull bf1b = pack2(bfq.z, bfq.w);

    const int seg = (tid >= 160 && tid < 320) ? 1 : 0;
    const int rr = (tid < 160) ? tid : (tid < 320 ? tid - 160 : 0);
    const int orow = rr / 20, ocol = rr - orow * 20;
    const int okbeg = seg * 128;
    const float bov = (tid < 160) ? __ldg(bo + ocol) : 0.f;
    float o_mem = 0.f, o_dfac = ALPHA, o_sumv = 0.f, o_mot = 0.f;

    const float* __restrict__ wr0g = g_WrT;
    const float* __restrict__ wf1g = g_WfT + 65536;
    const float* __restrict__ wr1g = g_WrT + 65536;

    const int kbeg = ks * 32;

    for (int t = 0; t < WIN; t++) {
        // ---- stage 1: layer0 partials (no ff0 dependency) ----
        ull acc[8][2];
#pragma unroll
        for (int r = 0; r < 8; r++) { acc[r][0] = 0ull; acc[r][1] = 0ull; }
        accum_quad_pf(acc, wr0g, hq4, sp0, kbeg);
#pragma unroll
        for (int r = 0; r < 8; r++)
            partq[(r * 8 + ks) * 64 + hq] = make_ulonglong2(acc[r][0], acc[r][1]);

        // wait for gemm tile (t, chunk): both column halves done
        if (tid == 0) {
            volatile int* fl = g_flags + (t * 4 + chunk);
            while (*fl != 2) __nanosleep(128);
        }
        __threadfence();
        __syncthreads();                                        // S1 (+ data ready)

        // ---- stage 2: reduce, membrane0, spikes ----
        {
            float4 ffv = ldg_cg128(g_ff0 + ((size_t)(b0 + ks) * WIN + t) * 256 + hq4);
            ull r0 = 0ull, r1 = 0ull;
#pragma unroll
            for (int j = 0; j < 8; j++) {
                ulonglong2 p = partq[(ks * 8 + j) * 64 + hq];
                r0 = add2(r0, p.x); r1 = add2(r1, p.y);
            }
            r0 = add2(r0, pack2(ffv.x, ffv.y));
            r1 = add2(r1, pack2(ffv.z, ffv.w));
            m0a = fma2n(m0a, df0a, r0);
            m0b = fma2n(m0b, df0b, r1);
            float mx, my, mz, mw;
            unpack2(m0a, mx, my); unpack2(m0b, mz, mw);
            float sx = (mx - THRESH > 0.f) ? 1.f : 0.f;
            float sy = (my - THRESH > 0.f) ? 1.f : 0.f;
            float sz = (mz - THRESH > 0.f) ? 1.f : 0.f;
            float sw = (mw - THRESH > 0.f) ? 1.f : 0.f;
            df0a = pack2(ALPHA * (1.f - sx), ALPHA * (1.f - sy));
            df0b = pack2(ALPHA * (1.f - sz), ALPHA * (1.f - sw));
            *(float2*)(sp0 + (hq4 + 0) * 20 + 2 * ks) = make_float2(sx, sx);
            *(float2*)(sp0 + (hq4 + 1) * 20 + 2 * ks) = make_float2(sy, sy);
            *(float2*)(sp0 + (hq4 + 2) * 20 + 2 * ks) = make_float2(sz, sz);
            *(float2*)(sp0 + (hq4 + 3) * 20 + 2 * ks) = make_float2(sw, sw);
        }
        __syncthreads();                                        // S2

        // ---- stage 3: layer1 partials ----
#pragma unroll
        for (int r = 0; r < 8; r++) { acc[r][0] = 0ull; acc[r][1] = 0ull; }
        accum_quad_pf(acc, wf1g, hq4, sp0, kbeg);
        accum_quad_pf(acc, wr1g, hq4, sp1, kbeg);
#pragma unroll
        for (int r = 0; r < 8; r++)
            partq[(r * 8 + ks) * 64 + hq] = make_ulonglong2(acc[r][0], acc[r][1]);
        __syncthreads();                                        // S3

        // ---- stage 4: reduce, membrane1, spikes ----
        {
            ull r0 = 0ull, r1 = 0ull;
#pragma unroll
            for (int j = 0; j < 8; j++) {
                ulonglong2 p = partq[(ks * 8 + j) * 64 + hq];
                r0 = add2(r0, p.x); r1 = add2(r1, p.y);
            }
            r0 = add2(r0, bf1a);
            r1 = add2(r1, bf1b);
            m1a = fma2n(m1a, df1a, r0);
            m1b = fma2n(m1b, df1b, r1);
            float mx, my, mz, mw;
            unpack2(m1a, mx, my); unpack2(m1b, mz, mw);
            float sx = (mx - THRESH > 0.f) ? 1.f : 0.f;
            float sy = (my - THRESH > 0.f) ? 1.f : 0.f;
            float sz = (mz - THRESH > 0.f) ? 1.f : 0.f;
            float sw = (mw - THRESH > 0.f) ? 1.f : 0.f;
            df1a = pack2(ALPHA * (1.f - sx), ALPHA * (1.f - sy));
            df1b = pack2(ALPHA * (1.f - sz), ALPHA * (1.f - sw));
            *(float2*)(sp1 + (hq4 + 0) * 20 + 2 * ks) = make_float2(sx, sx);
            *(float2*)(sp1 + (hq4 + 1) * 20 + 2 * ks) = make_float2(sy, sy);
            *(float2*)(sp1 + (hq4 + 2) * 20 + 2 * ks) = make_float2(sz, sz);
            *(float2*)(sp1 + (hq4 + 3) * 20 + 2 * ks) = make_float2(sw, sw);
        }
        __syncthreads();                                        // S4

        // ---- stage 5: output partials ----
        if (tid < 320) {
            float oa = 0.f;
#pragma unroll 8
            for (int k = okbeg; k < okbeg + 128; k++) {
                oa += sp1[k * 20 + 2 * orow] * wot[k * 20 + ocol];
            }
            opart[tid] = oa;
        }
        __syncthreads();                                        // S5

        // ---- stage 6: output membrane ----
        if (tid < 160) {
            float oa = opart[tid] + opart[tid + 160] + bov;
            o_mem = o_mem * o_dfac + oa;
            float os = (o_mem - THRESH > 0.f) ? 1.f : 0.f;
            o_dfac = ALPHA * (1.f - os);
            o_sumv += os;
            osm[tid] = o_mem;
        }
        __syncthreads();                                        // S6

        // ---- stage 7: distributed softmax ----
        float e = 0.f;
        if (tid < 160) {
            float mx = -1e30f;
#pragma unroll
            for (int o = 0; o < 20; o++) mx = fmaxf(mx, osm[orow * 20 + o]);
            e = expf(o_mem - mx);
            otmp[tid] = e;
        }
        __syncthreads();                                        // S7

        if (tid < 160) {
            float s = 0.f;
#pragma unroll
            for (int o = 0; o < 20; o++) s += otmp[orow * 20 + o];
            o_mot += e / s;
        }
        // no sync needed: otmp rewritten only after S6 of next step
    }

    if (tid < 160) {
        int b = b0 + orow;
        out[b * 20 + ocol] = o_sumv / (float)WIN;
        out[BATCH * 20 + b * 20 + ocol] = o_mot;
    }
}

// ---------------- launch ----------------
extern "C" void kernel_launch(void* const* d_in, const int* in_sizes, int n_in,
                              void* d_out, int out_size) {
    const float* x  = (const float*)d_in[0];
    const float* Wd = (const float*)d_in[1];
    const float* bd = (const float*)d_in[2];
    const float* Wf = (const float*)d_in[3];
    const float* bf = (const float*)d_in[4];
    const float* Wr = (const float*)d_in[5];
    const float* Wo = (const float*)d_in[6];
    const float* bo = (const float*)d_in[7];
    float* out = (float*)d_out;

    static bool attr_set = false;
    if (!attr_set) {
        cudaFuncSetAttribute(fused_kernel, cudaFuncAttributeMaxDynamicSharedMemorySize,
                             SCAN_FLOATS * 4);
        attr_set = true;
    }

    prep_transpose<<<512, 256>>>(Wf, Wr, Wo);
    prep_wc_cvec<<<3 * NUM_INPUT + 1, 256>>>(Wd, bd, bf);
    fused_kernel<<<FK_SCAN_BLOCKS + FK_GEMM_BLOCKS, 512, SCAN_FLOATS * 4>>>(x, bf, bo, out);
}

// round 15
// speedup vs baseline: 1.5375x; 1.5375x over previous
#include <cuda_runtime.h>
#include <cstdint>

#define NUM_INPUT  700
#define NUM_HIDDEN 256
#define NUM_OUTPUT 20
#define WIN        50
#define BATCH      512
#define THRESH     0.3f
#define ALPHA      0.8f

#define M_ROWS (BATCH * WIN)   // 25600

typedef unsigned long long ull;

// ---------------- f32x2 helpers ----------------
__device__ __forceinline__ ull pack2(float x, float y) {
    ull r; asm("mov.b64 %0, {%1, %2};" : "=l"(r) : "f"(x), "f"(y)); return r;
}
__device__ __forceinline__ void unpack2(ull v, float& x, float& y) {
    asm("mov.b64 {%0, %1}, %2;" : "=f"(x), "=f"(y) : "l"(v));
}
__device__ __forceinline__ void ffma2(ull& d, ull a, ull b) {   // d = a*b + d
    asm("fma.rn.f32x2 %0, %1, %2, %0;" : "+l"(d) : "l"(a), "l"(b));
}
__device__ __forceinline__ ull fma2n(ull a, ull b, ull c) {     // a*b + c
    ull d; asm("fma.rn.f32x2 %0, %1, %2, %3;" : "=l"(d) : "l"(a), "l"(b), "l"(c)); return d;
}
__device__ __forceinline__ ull add2(ull a, ull b) {
    ull d; asm("add.rn.f32x2 %0, %1, %2;" : "=l"(d) : "l"(a), "l"(b)); return d;
}
__device__ __forceinline__ ulonglong2 ldg128(const float* p) {
    ulonglong2 v;
    asm("ld.global.nc.v2.u64 {%0, %1}, [%2];" : "=l"(v.x), "=l"(v.y) : "l"(p));
    return v;
}
// coherent (L2) 128-bit load: for data written earlier in the SAME launch
__device__ __forceinline__ float4 ldg_cg128(const float* p) {
    float4 v;
    asm volatile("ld.global.cg.v4.f32 {%0,%1,%2,%3}, [%4];"
                 : "=f"(v.x), "=f"(v.y), "=f"(v.z), "=f"(v.w) : "l"(p));
    return v;
}

// ---------------- device scratch ----------------
__device__ float g_WcT[3 * NUM_INPUT * NUM_HIDDEN];
__device__ float g_WfT[2 * NUM_HIDDEN * NUM_HIDDEN];
__device__ float g_WrT[2 * NUM_HIDDEN * NUM_HIDDEN];
__device__ float g_WoT[NUM_HIDDEN * NUM_OUTPUT];
__device__ float g_cvec[NUM_HIDDEN];
__device__ float g_ff0[M_ROWS * NUM_HIDDEN];
__device__ int   g_flags[4 * WIN];          // per (t, chunk) tile counter (2 colhalves)

// ---------------- prep kernels ----------------
__global__ void prep_transpose(const float* __restrict__ Wf,
                               const float* __restrict__ Wr,
                               const float* __restrict__ Wo) {
    int idx = blockIdx.x * 256 + threadIdx.x;
    if (idx < 4 * WIN) g_flags[idx] = 0;
    if (idx < 2 * 256 * 256) {
        int h = idx & 255;
        int k = (idx >> 8) & 255;
        int l = idx >> 16;
        g_WfT[(l * 256 + k) * 256 + h] = Wf[(l * 256 + h) * 256 + k];
        g_WrT[(l * 256 + k) * 256 + h] = Wr[(l * 256 + h) * 256 + k];
    }
    if (idx < 256 * 20) {
        int o = idx % 20;
        int k = idx / 20;
        g_WoT[k * 20 + o] = Wo[o * 256 + k];
    }
}

// wc blocks 0..2099, cvec block 2100 (bit-identical to the R11 separate kernels)
__global__ void prep_wc_cvec(const float* __restrict__ Wd,
                             const float* __restrict__ bd,
                             const float* __restrict__ bf) {
    if (blockIdx.x < 3 * NUM_INPUT) {
        int ik = blockIdx.x;
        int i = ik / NUM_INPUT;
        int k = ik % NUM_INPUT;
        int h = threadIdx.x;
        float s = 0.f;
#pragma unroll 8
        for (int j = 0; j < 256; j++) {
            s += g_WfT[j * 256 + h] * __ldg(&Wd[(i * 256 + j) * NUM_INPUT + k]);
        }
        g_WcT[(i * NUM_INPUT + k) * 256 + h] = s;
    } else {
        int h = threadIdx.x;
        float s = bf[h];
#pragma unroll 8
        for (int j = 0; j < 256; j++) {
            float bsum = bd[j] + bd[256 + j] + bd[512 + j];
            s += bsum * g_WfT[j * 256 + h];
        }
        g_cvec[h] = s;
    }
}

// ---------------- fused kernel ----------------
// blocks 0..63: scan (one per 8 batch rows). blocks 64..463: gemm tiles.
// gemm tile gid-64: tile = (gid-64)>>1 in t-ascending order, colhalf = (gid-64)&1.
#define FK_SCAN_BLOCKS 64
#define FK_GEMM_BLOCKS 400

// scan smem layout (floats)
#define OFFP    0
#define OFFS0   16384
#define OFFS1   (OFFS0 + 5120)
#define OFFWOT  (OFFS1 + 5120)
#define OFFOSM  (OFFWOT + 5120)
#define OFFOTMP (OFFOSM + 160)
#define SCAN_FLOATS (OFFOTMP + 160)    // 32064 floats = 128256 bytes

__device__ __forceinline__ void accum_quad_pf(ull acc[8][2], const float* __restrict__ wg,
                                              int hq4, const float* __restrict__ sp, int kbeg) {
    const float* wp = wg + (size_t)kbeg * 256 + hq4;
    ulonglong2 wbuf[2][4];
#pragma unroll
    for (int cc = 0; cc < 4; cc++) wbuf[0][cc] = ldg128(wp + cc * 256);
#pragma unroll
    for (int j = 0; j < 8; j++) {
        const int cur = j & 1, nxt = cur ^ 1;
        if (j < 7) {
            const float* q = wp + (size_t)((j + 1) * 4) * 256;
#pragma unroll
            for (int cc = 0; cc < 4; cc++) wbuf[nxt][cc] = ldg128(q + cc * 256);
        }
#pragma unroll
        for (int cc = 0; cc < 4; cc++) {
            const int k = kbeg + j * 4 + cc;
            const ulonglong2* sq = (const ulonglong2*)(sp + k * 20);
            ulonglong2 s01 = sq[0], s23 = sq[1], s45 = sq[2], s67 = sq[3];
            ulonglong2 w = wbuf[cur][cc];
            ffma2(acc[0][0], w.x, s01.x); ffma2(acc[0][1], w.y, s01.x);
            ffma2(acc[1][0], w.x, s01.y); ffma2(acc[1][1], w.y, s01.y);
            ffma2(acc[2][0], w.x, s23.x); ffma2(acc[2][1], w.y, s23.x);
            ffma2(acc[3][0], w.x, s23.y); ffma2(acc[3][1], w.y, s23.y);
            ffma2(acc[4][0], w.x, s45.x); ffma2(acc[4][1], w.y, s45.x);
            ffma2(acc[5][0], w.x, s45.y); ffma2(acc[5][1], w.y, s45.y);
            ffma2(acc[6][0], w.x, s67.x); ffma2(acc[6][1], w.y, s67.x);
            ffma2(acc[7][0], w.x, s67.y); ffma2(acc[7][1], w.y, s67.y);
        }
    }
}

__global__ __launch_bounds__(512, 1) void fused_kernel(const float* __restrict__ x,
                                                       const float* __restrict__ bf,
                                                       const float* __restrict__ bo,
                                                       float* __restrict__ out) {
    extern __shared__ float sm[];
    const int tid = threadIdx.x;

    if (blockIdx.x >= FK_SCAN_BLOCKS) {
        // ==================== GEMM tile (R11 exact) ====================
        const int gid = blockIdx.x - FK_SCAN_BLOCKS;
        const int tile = gid >> 1;              // 0..199, t-ascending
        const int h0 = (gid & 1) << 7;          // 0 or 128
        const int t = tile >> 2;
        const int b0g = (tile & 3) << 7;

        float (*As)[132] = reinterpret_cast<float(*)[132]>(sm);
        float (*Bs)[128] = reinterpret_cast<float(*)[128]>(sm + 16 * 132);

        const int lane = tid & 31;
        const int warp = tid >> 5;
        const int arow = tid >> 2;              // 0..127
        const int akq  = (tid & 3) * 4;         // 0,4,8,12
        const int bk   = tid >> 5;              // 0..15
        const int bcol = lane * 4;

        ull accp[4][4];
#pragma unroll
        for (int p = 0; p < 4; p++)
#pragma unroll
            for (int j = 0; j < 4; j++) accp[p][j] = 0ull;

        for (int seg = 0; seg < 3; seg++) {
            const int d = seg * 16;
            if (t < d) continue;
            const int ts = t - d;
            const float* __restrict__ xrow = x + ((size_t)(b0g + arow) * WIN + ts) * NUM_INPUT;
            const float* __restrict__ Bsrc = g_WcT + (size_t)seg * NUM_INPUT * 256;

            for (int kb = 0; kb < 704; kb += 16) {
                int kg = kb + akq;
                float4 v = make_float4(0.f, 0.f, 0.f, 0.f);
                if (kg < NUM_INPUT) v = __ldg((const float4*)(xrow + kg));
                As[akq + 0][arow] = v.x;
                As[akq + 1][arow] = v.y;
                As[akq + 2][arow] = v.z;
                As[akq + 3][arow] = v.w;

                int kg2 = kb + bk;
                float4 w = make_float4(0.f, 0.f, 0.f, 0.f);
                if (kg2 < NUM_INPUT)
                    w = __ldg((const float4*)(Bsrc + (size_t)kg2 * 256 + h0 + bcol));
                *(float4*)&Bs[bk][bcol] = w;

                __syncthreads();
#pragma unroll
                for (int kk = 0; kk < 16; kk++) {
                    ulonglong2 a01 = *(const ulonglong2*)&As[kk][warp * 8 + 0];
                    ulonglong2 a23 = *(const ulonglong2*)&As[kk][warp * 8 + 4];
                    float4 bb = *(const float4*)&Bs[kk][lane * 4];
                    ull bp[4] = {pack2(bb.x, bb.x), pack2(bb.y, bb.y),
                                 pack2(bb.z, bb.z), pack2(bb.w, bb.w)};
                    ull ap[4] = {a01.x, a01.y, a23.x, a23.y};
#pragma unroll
                    for (int p = 0; p < 4; p++)
#pragma unroll
                        for (int j = 0; j < 4; j++) ffma2(accp[p][j], ap[p], bp[j]);
                }
                __syncthreads();
            }
        }

        // epilogue: + cvec, store t-major rows; then publish flag
        {
            float4 cv = __ldg((const float4*)(g_cvec + h0 + lane * 4));
#pragma unroll
            for (int p = 0; p < 4; p++) {
                float lo[4], hi[4];
#pragma unroll
                for (int j = 0; j < 4; j++) unpack2(accp[p][j], lo[j], hi[j]);
                float4 o0 = make_float4(lo[0] + cv.x, lo[1] + cv.y, lo[2] + cv.z, lo[3] + cv.w);
                float4 o1 = make_float4(hi[0] + cv.x, hi[1] + cv.y, hi[2] + cv.z, hi[3] + cv.w);
                int r0 = b0g + warp * 8 + 2 * p;
                *(float4*)(g_ff0 + ((size_t)r0 * WIN + t) * 256 + h0 + lane * 4) = o0;
                *(float4*)(g_ff0 + ((size_t)(r0 + 1) * WIN + t) * 256 + h0 + lane * 4) = o1;
            }
        }
        __threadfence();
        __syncthreads();
        if (tid == 0) atomicAdd(&g_flags[tile], 1);
        return;
    }

    // ==================== SCAN block (R11 exact) ====================
    ulonglong2* partq = (ulonglong2*)(sm + OFFP);
    float* sp0  = sm + OFFS0;
    float* sp1  = sm + OFFS1;
    float* wot  = sm + OFFWOT;
    float* opart = sm + OFFP;          // alias (barrier-separated)
    float* osm  = sm + OFFOSM;
    float* otmp = sm + OFFOTMP;

    const int ks = tid >> 6;
    const int hq = tid & 63;
    const int hq4 = hq * 4;
    const int b0 = blockIdx.x * 8;
    const int chunk = blockIdx.x >> 4;         // 128-batch chunk

    for (int i = tid; i < 256 * 20; i += 512) wot[i] = g_WoT[i];
    for (int i = tid; i < 5120; i += 512) { sp0[i] = 0.f; sp1[i] = 0.f; }
    __syncthreads();

    ull m0a = 0, m0b = 0, m1a = 0, m1b = 0;
    const ull alpha2 = pack2(ALPHA, ALPHA);
    ull df0a = alpha2, df0b = alpha2, df1a = alpha2, df1b = alpha2;

    float4 bfq = __ldg((const float4*)(bf + 256 + hq4));
    const ull bf1a = pack2(bfq.x, bfq.y);
    const ull bf1b = pack2(bfq.z, bfq.w);

    const int seg = (tid >= 160 && tid < 320) ? 1 : 0;
    const int rr = (tid < 160) ? tid : (tid < 320 ? tid - 160 : 0);
    const int orow = rr / 20, ocol = rr - orow * 20;
    const int okbeg = seg * 128;
    const float bov = (tid < 160) ? __ldg(bo + ocol) : 0.f;
    float o_mem = 0.f, o_dfac = ALPHA, o_sumv = 0.f, o_mot = 0.f;

    const float* __restrict__ wr0g = g_WrT;
    const float* __restrict__ wf1g = g_WfT + 65536;
    const float* __restrict__ wr1g = g_WrT + 65536;

    const int kbeg = ks * 32;

    for (int t = 0; t < WIN; t++) {
        // ---- stage 1: layer0 partials (no ff0 dependency) ----
        ull acc[8][2];
#pragma unroll
        for (int r = 0; r < 8; r++) { acc[r][0] = 0ull; acc[r][1] = 0ull; }
        accum_quad_pf(acc, wr0g, hq4, sp0, kbeg);
#pragma unroll
        for (int r = 0; r < 8; r++)
            partq[(r * 8 + ks) * 64 + hq] = make_ulonglong2(acc[r][0], acc[r][1]);

        // wait for gemm tile (t, chunk): both column halves done
        if (tid == 0) {
            volatile int* fl = g_flags + (t * 4 + chunk);
            while (*fl != 2) __nanosleep(128);
        }
        __threadfence();
        __syncthreads();                                        // S1 (+ data ready)

        // ---- stage 2: reduce, membrane0, spikes ----
        {
            float4 ffv = ldg_cg128(g_ff0 + ((size_t)(b0 + ks) * WIN + t) * 256 + hq4);
            ull r0 = 0ull, r1 = 0ull;
#pragma unroll
            for (int j = 0; j < 8; j++) {
                ulonglong2 p = partq[(ks * 8 + j) * 64 + hq];
                r0 = add2(r0, p.x); r1 = add2(r1, p.y);
            }
            r0 = add2(r0, pack2(ffv.x, ffv.y));
            r1 = add2(r1, pack2(ffv.z, ffv.w));
            m0a = fma2n(m0a, df0a, r0);
            m0b = fma2n(m0b, df0b, r1);
            float mx, my, mz, mw;
            unpack2(m0a, mx, my); unpack2(m0b, mz, mw);
            float sx = (mx - THRESH > 0.f) ? 1.f : 0.f;
            float sy = (my - THRESH > 0.f) ? 1.f : 0.f;
            float sz = (mz - THRESH > 0.f) ? 1.f : 0.f;
            float sw = (mw - THRESH > 0.f) ? 1.f : 0.f;
            df0a = pack2(ALPHA * (1.f - sx), ALPHA * (1.f - sy));
            df0b = pack2(ALPHA * (1.f - sz), ALPHA * (1.f - sw));
            *(float2*)(sp0 + (hq4 + 0) * 20 + 2 * ks) = make_float2(sx, sx);
            *(float2*)(sp0 + (hq4 + 1) * 20 + 2 * ks) = make_float2(sy, sy);
            *(float2*)(sp0 + (hq4 + 2) * 20 + 2 * ks) = make_float2(sz, sz);
            *(float2*)(sp0 + (hq4 + 3) * 20 + 2 * ks) = make_float2(sw, sw);
        }
        __syncthreads();                                        // S2

        // ---- stage 3: layer1 partials ----
#pragma unroll
        for (int r = 0; r < 8; r++) { acc[r][0] = 0ull; acc[r][1] = 0ull; }
        accum_quad_pf(acc, wf1g, hq4, sp0, kbeg);
        accum_quad_pf(acc, wr1g, hq4, sp1, kbeg);
#pragma unroll
        for (int r = 0; r < 8; r++)
            partq[(r * 8 + ks) * 64 + hq] = make_ulonglong2(acc[r][0], acc[r][1]);
        __syncthreads();                                        // S3

        // ---- stage 4: reduce, membrane1, spikes ----
        {
            ull r0 = 0ull, r1 = 0ull;
#pragma unroll
            for (int j = 0; j < 8; j++) {
                ulonglong2 p = partq[(ks * 8 + j) * 64 + hq];
                r0 = add2(r0, p.x); r1 = add2(r1, p.y);
            }
            r0 = add2(r0, bf1a);
            r1 = add2(r1, bf1b);
            m1a = fma2n(m1a, df1a, r0);
            m1b = fma2n(m1b, df1b, r1);
            float mx, my, mz, mw;
            unpack2(m1a, mx, my); unpack2(m1b, mz, mw);
            float sx = (mx - THRESH > 0.f) ? 1.f : 0.f;
            float sy = (my - THRESH > 0.f) ? 1.f : 0.f;
            float sz = (mz - THRESH > 0.f) ? 1.f : 0.f;
            float sw = (mw - THRESH > 0.f) ? 1.f : 0.f;
            df1a = pack2(ALPHA * (1.f - sx), ALPHA * (1.f - sy));
            df1b = pack2(ALPHA * (1.f - sz), ALPHA * (1.f - sw));
            *(float2*)(sp1 + (hq4 + 0) * 20 + 2 * ks) = make_float2(sx, sx);
            *(float2*)(sp1 + (hq4 + 1) * 20 + 2 * ks) = make_float2(sy, sy);
            *(float2*)(sp1 + (hq4 + 2) * 20 + 2 * ks) = make_float2(sz, sz);
            *(float2*)(sp1 + (hq4 + 3) * 20 + 2 * ks) = make_float2(sw, sw);
        }
        __syncthreads();                                        // S4

        // ---- stage 5: output partials ----
        if (tid < 320) {
            float oa = 0.f;
#pragma unroll 8
            for (int k = okbeg; k < okbeg + 128; k++) {
                oa += sp1[k * 20 + 2 * orow] * wot[k * 20 + ocol];
            }
            opart[tid] = oa;
        }
        __syncthreads();                                        // S5

        // ---- stage 6: output membrane ----
        if (tid < 160) {
            float oa = opart[tid] + opart[tid + 160] + bov;
            o_mem = o_mem * o_dfac + oa;
            float os = (o_mem - THRESH > 0.f) ? 1.f : 0.f;
            o_dfac = ALPHA * (1.f - os);
            o_sumv += os;
            osm[tid] = o_mem;
        }
        __syncthreads();                                        // S6

        // ---- stage 7: distributed softmax ----
        float e = 0.f;
        if (tid < 160) {
            float mx = -1e30f;
#pragma unroll
            for (int o = 0; o < 20; o++) mx = fmaxf(mx, osm[orow * 20 + o]);
            e = expf(o_mem - mx);
            otmp[tid] = e;
        }
        __syncthreads();                                        // S7

        if (tid < 160) {
            float s = 0.f;
#pragma unroll
            for (int o = 0; o < 20; o++) s += otmp[orow * 20 + o];
            o_mot += e / s;
        }
        // no sync needed: otmp rewritten only after S6 of next step
    }

    if (tid < 160) {
        int b = b0 + orow;
        out[b * 20 + ocol] = o_sumv / (float)WIN;
        out[BATCH * 20 + b * 20 + ocol] = o_mot;
    }
}

// ---------------- launch ----------------
extern "C" void kernel_launch(void* const* d_in, const int* in_sizes, int n_in,
                              void* d_out, int out_size) {
    const float* x  = (const float*)d_in[0];
    const float* Wd = (const float*)d_in[1];
    const float* bd = (const float*)d_in[2];
    const float* Wf = (const float*)d_in[3];
    const float* bf = (const float*)d_in[4];
    const float* Wr = (const float*)d_in[5];
    const float* Wo = (const float*)d_in[6];
    const float* bo = (const float*)d_in[7];
    float* out = (float*)d_out;

    static bool attr_set = false;
    if (!attr_set) {
        cudaFuncSetAttribute(fused_kernel, cudaFuncAttributeMaxDynamicSharedMemorySize,
                             SCAN_FLOATS * 4);
        attr_set = true;
    }

    prep_transpose<<<512, 256>>>(Wf, Wr, Wo);
    prep_wc_cvec<<<3 * NUM_INPUT + 1, 256>>>(Wd, bd, bf);
    fused_kernel<<<FK_SCAN_BLOCKS + FK_GEMM_BLOCKS, 512, SCAN_FLOATS * 4>>>(x, bf, bo, out);
}